// round 1
// baseline (speedup 1.0000x reference)
#include <cuda_runtime.h>
#include <math.h>

#define NN   50000
#define FIN  256
#define H1N  8
#define HIDD 32
#define F1   256     // H1*HID
#define F2   64
#define NEG  0.2f

// ---------------- scratch (device globals; no allocation allowed) ----------------
__device__ float g_h1[NN * F1];          // layer1 projection
__device__ float g_el1[NN * H1N];
__device__ float g_er1[NN * H1N];
__device__ float g_x1[NN * F1];          // layer1 output (post-ELU)
__device__ float g_h2res[NN * 128];      // [h2 (64) | residual (64)]
__device__ float g_el2[NN];
__device__ float g_er2[NN];
__device__ float g_Bcat[FIN * 128];      // [W2 | res_W2] concatenated
__device__ int   g_deg[NN];
__device__ int   g_off[NN + 1];
__device__ int   g_perm[900000];         // E = 850000

// ---------------- CSR build ----------------
__global__ void k_zero_int(int* a, int n) {
    int i = blockIdx.x * blockDim.x + threadIdx.x;
    if (i < n) a[i] = 0;
}

__global__ void k_hist(const int* __restrict__ dst, int E, int* __restrict__ deg) {
    int i = blockIdx.x * blockDim.x + threadIdx.x;
    if (i < E) atomicAdd(&deg[dst[i]], 1);
}

// single-block exclusive scan (N=50000 -> 49 chunks of 1024)
__global__ void k_scan(const int* __restrict__ deg, int* __restrict__ off, int n) {
    __shared__ int wsum[32];
    __shared__ int carry;
    int tid = threadIdx.x, lane = tid & 31, wid = tid >> 5;
    if (tid == 0) carry = 0;
    __syncthreads();
    for (int base = 0; base < n; base += 1024) {
        int i = base + tid;
        int v = (i < n) ? deg[i] : 0;
        int x = v;
        #pragma unroll
        for (int o = 1; o < 32; o <<= 1) {
            int y = __shfl_up_sync(0xffffffffu, x, o);
            if (lane >= o) x += y;
        }
        if (lane == 31) wsum[wid] = x;
        __syncthreads();
        if (wid == 0) {
            int w = wsum[lane];
            #pragma unroll
            for (int o = 1; o < 32; o <<= 1) {
                int y = __shfl_up_sync(0xffffffffu, w, o);
                if (lane >= o) w += y;
            }
            wsum[lane] = w;
        }
        __syncthreads();
        int incl = x + (wid ? wsum[wid - 1] : 0) + carry;
        if (i < n) off[i] = incl - v;
        __syncthreads();
        if (tid == 1023) carry = incl;
        __syncthreads();
    }
    if (tid == 0) off[n] = carry;
}

__global__ void k_scatter(const int* __restrict__ dst, int E,
                          const int* __restrict__ off, int* __restrict__ cur,
                          int* __restrict__ perm) {
    int i = blockIdx.x * blockDim.x + threadIdx.x;
    if (i < E) {
        int d = dst[i];
        int p = off[d] + atomicAdd(&cur[d], 1);
        perm[p] = i;
    }
}

// ---------------- SGEMM: C[M,N] = A[M,K] @ B[K,N] ----------------
// BM=64, BN=64, BK=16, 256 threads, 4x4 per thread. N,K multiples of tile; M guarded.
__global__ void k_sgemm(const float* __restrict__ A, const float* __restrict__ B,
                        float* __restrict__ C, int M, int N, int K) {
    __shared__ float As[16][64];
    __shared__ float Bs[16][64];
    int bm = blockIdx.x * 64, bn = blockIdx.y * 64;
    int t = threadIdx.x;
    int tx = t & 15, ty = t >> 4;
    float acc[4][4] = {};
    int arow = t >> 2;          // 0..63
    int ak   = (t & 3) * 4;     // 0,4,8,12
    int brow = t >> 4;          // 0..15
    int bc   = (t & 15) * 4;

    for (int kt = 0; kt < K; kt += 16) {
        float4 av = make_float4(0.f, 0.f, 0.f, 0.f);
        if (bm + arow < M)
            av = *(const float4*)&A[(size_t)(bm + arow) * K + kt + ak];
        As[ak + 0][arow] = av.x;
        As[ak + 1][arow] = av.y;
        As[ak + 2][arow] = av.z;
        As[ak + 3][arow] = av.w;
        float4 bv = *(const float4*)&B[(size_t)(kt + brow) * N + bn + bc];
        *(float4*)&Bs[brow][bc] = bv;
        __syncthreads();
        #pragma unroll
        for (int kk = 0; kk < 16; kk++) {
            float4 a = *(float4*)&As[kk][ty * 4];
            float4 b = *(float4*)&Bs[kk][tx * 4];
            float ar[4] = {a.x, a.y, a.z, a.w};
            float br[4] = {b.x, b.y, b.z, b.w};
            #pragma unroll
            for (int i = 0; i < 4; i++)
                #pragma unroll
                for (int j = 0; j < 4; j++)
                    acc[i][j] += ar[i] * br[j];
        }
        __syncthreads();
    }
    #pragma unroll
    for (int i = 0; i < 4; i++) {
        int r = bm + ty * 4 + i;
        if (r < M) {
            float4 o = make_float4(acc[i][0], acc[i][1], acc[i][2], acc[i][3]);
            *(float4*)&C[(size_t)r * N + bn + tx * 4] = o;
        }
    }
}

// ---------------- attention dot products ----------------
// warp per node: el[n][h] = sum_f h1[n][h*32+f]*attn_l[h][f]
__global__ void k_attn1(const float* __restrict__ h1, const float* __restrict__ al,
                        const float* __restrict__ ar, float* __restrict__ el,
                        float* __restrict__ er) {
    int w = (blockIdx.x * blockDim.x + threadIdx.x) >> 5;
    if (w >= NN) return;
    int lane = threadIdx.x & 31;
    const float* hp = h1 + (size_t)w * F1;
    float se[8], sr[8];
    #pragma unroll
    for (int j = 0; j < 8; j++) {
        float h = hp[lane + 32 * j];
        se[j] = h * al[j * 32 + lane];
        sr[j] = h * ar[j * 32 + lane];
    }
    #pragma unroll
    for (int j = 0; j < 8; j++) {
        #pragma unroll
        for (int o = 16; o; o >>= 1) {
            se[j] += __shfl_xor_sync(0xffffffffu, se[j], o);
            sr[j] += __shfl_xor_sync(0xffffffffu, sr[j], o);
        }
    }
    #pragma unroll
    for (int j = 0; j < 8; j++) {
        if (lane == j) {
            el[w * 8 + j] = se[j];
            er[w * 8 + j] = sr[j];
        }
    }
}

__global__ void k_attn2(const float* __restrict__ h2res, const float* __restrict__ al,
                        const float* __restrict__ ar, float* __restrict__ el,
                        float* __restrict__ er) {
    int w = (blockIdx.x * blockDim.x + threadIdx.x) >> 5;
    if (w >= NN) return;
    int lane = threadIdx.x & 31;
    const float* hp = h2res + (size_t)w * 128;
    float h0 = hp[lane], h1v = hp[lane + 32];
    float a = h0 * al[lane] + h1v * al[lane + 32];
    float b = h0 * ar[lane] + h1v * ar[lane + 32];
    #pragma unroll
    for (int o = 16; o; o >>= 1) {
        a += __shfl_xor_sync(0xffffffffu, a, o);
        b += __shfl_xor_sync(0xffffffffu, b, o);
    }
    if (lane == 0) { el[w] = a; er[w] = b; }
}

// ---------------- layer-1 aggregation (warp per dst node) ----------------
__global__ void k_agg1(const int* __restrict__ src, const int* __restrict__ perm,
                       const int* __restrict__ off, const float* __restrict__ h1,
                       const float* __restrict__ el, const float* __restrict__ er,
                       const float* __restrict__ feats, const float* __restrict__ bias,
                       float* __restrict__ x1) {
    int w = (blockIdx.x * blockDim.x + threadIdx.x) >> 5;
    if (w >= NN) return;
    int lane = threadIdx.x & 31;
    int s0 = off[w], s1 = off[w + 1];
    float erv[8], m[8], sum[8];
    #pragma unroll
    for (int j = 0; j < 8; j++) { erv[j] = er[w * 8 + j]; m[j] = -1e30f; sum[j] = 0.f; }

    // pass 1: online max + exp-sum per head
    for (int base = s0; base < s1; base += 32) {
        int idx = base + lane;
        bool val = idx < s1;
        int u = val ? src[perm[idx]] : 0;
        #pragma unroll
        for (int j = 0; j < 8; j++) {
            float e;
            if (val) { float t = el[u * 8 + j] + erv[j]; e = t > 0.f ? t : NEG * t; }
            else e = -1e30f;
            float cm = e;
            #pragma unroll
            for (int o = 16; o; o >>= 1) cm = fmaxf(cm, __shfl_xor_sync(0xffffffffu, cm, o));
            float nm = fmaxf(m[j], cm);
            float ex = val ? __expf(e - nm) : 0.f;
            float cs = ex;
            #pragma unroll
            for (int o = 16; o; o >>= 1) cs += __shfl_xor_sync(0xffffffffu, cs, o);
            sum[j] = sum[j] * __expf(m[j] - nm) + cs;
            m[j] = nm;
        }
    }

    // per-lane scalars for head = lane (lanes 0..7)
    float m_l = 0.f, is_l = 0.f, er_l = 0.f;
    #pragma unroll
    for (int j = 0; j < 8; j++)
        if (lane == j) { m_l = m[j]; is_l = 1.f / sum[j]; er_l = erv[j]; }

    // pass 2: weighted gather. feature f = lane + 32*j => head j.
    float acc[8] = {0.f, 0.f, 0.f, 0.f, 0.f, 0.f, 0.f, 0.f};
    for (int i = s0; i < s1; i++) {
        int u = src[perm[i]];
        float alpha = 0.f;
        if (lane < 8) {
            float t = el[u * 8 + lane] + er_l;
            float e = t > 0.f ? t : NEG * t;
            alpha = __expf(e - m_l) * is_l;
        }
        const float* hu = h1 + (size_t)u * F1;
        #pragma unroll
        for (int j = 0; j < 8; j++) {
            float a = __shfl_sync(0xffffffffu, alpha, j);
            acc[j] += hu[lane + 32 * j] * a;
        }
    }

    // residual (identity) + bias + ELU
    #pragma unroll
    for (int j = 0; j < 8; j++) {
        int f = lane + 32 * j;
        float r = acc[j] + feats[(size_t)w * FIN + f] + bias[f];
        x1[(size_t)w * F1 + f] = r > 0.f ? r : expm1f(r);
    }
}

// ---------------- concat [W2 | res_W2] ----------------
__global__ void k_concat(const float* __restrict__ W2, const float* __restrict__ rw,
                         float* __restrict__ Bcat) {
    int i = blockIdx.x * blockDim.x + threadIdx.x;
    if (i < FIN * 128) {
        int k = i >> 7, c = i & 127;
        Bcat[i] = (c < 64) ? W2[k * 64 + c] : rw[k * 64 + (c - 64)];
    }
}

// ---------------- layer-2 aggregation (warp per dst node) ----------------
__global__ void k_agg2(const int* __restrict__ src, const int* __restrict__ perm,
                       const int* __restrict__ off, const float* __restrict__ h2res,
                       const float* __restrict__ el, const float* __restrict__ er,
                       const float* __restrict__ bias, float* __restrict__ out) {
    int w = (blockIdx.x * blockDim.x + threadIdx.x) >> 5;
    if (w >= NN) return;
    int lane = threadIdx.x & 31;
    int s0 = off[w], s1 = off[w + 1];
    float erv = er[w];
    float m = -1e30f, s = 0.f;
    for (int base = s0; base < s1; base += 32) {
        int idx = base + lane;
        bool val = idx < s1;
        int u = val ? src[perm[idx]] : 0;
        float e;
        if (val) { float t = el[u] + erv; e = t > 0.f ? t : NEG * t; }
        else e = -1e30f;
        float cm = e;
        #pragma unroll
        for (int o = 16; o; o >>= 1) cm = fmaxf(cm, __shfl_xor_sync(0xffffffffu, cm, o));
        float nm = fmaxf(m, cm);
        float ex = val ? __expf(e - nm) : 0.f;
        float cs = ex;
        #pragma unroll
        for (int o = 16; o; o >>= 1) cs += __shfl_xor_sync(0xffffffffu, cs, o);
        s = s * __expf(m - nm) + cs;
        m = nm;
    }
    float is = 1.f / s;
    float a0 = 0.f, a1 = 0.f;
    for (int i = s0; i < s1; i++) {
        int u = src[perm[i]];
        float t = el[u] + erv;
        float e = t > 0.f ? t : NEG * t;
        float alpha = __expf(e - m) * is;
        const float* hu = h2res + (size_t)u * 128;
        a0 += hu[lane] * alpha;
        a1 += hu[lane + 32] * alpha;
    }
    const float* rv = h2res + (size_t)w * 128 + 64;
    out[(size_t)w * 64 + lane]      = a0 + rv[lane]      + bias[lane];
    out[(size_t)w * 64 + lane + 32] = a1 + rv[lane + 32] + bias[lane + 32];
}

// ---------------- launch ----------------
extern "C" void kernel_launch(void* const* d_in, const int* in_sizes, int n_in,
                              void* d_out, int out_size) {
    const float* feats = (const float*)d_in[0];
    const int*   src   = (const int*)d_in[1];
    const int*   dst   = (const int*)d_in[2];
    const float* W1    = (const float*)d_in[3];
    const float* al1   = (const float*)d_in[4];
    const float* ar1   = (const float*)d_in[5];
    const float* b1    = (const float*)d_in[6];
    const float* W2    = (const float*)d_in[7];
    const float* al2   = (const float*)d_in[8];
    const float* ar2   = (const float*)d_in[9];
    const float* b2    = (const float*)d_in[10];
    const float* rw2   = (const float*)d_in[11];
    float* out = (float*)d_out;
    int E = in_sizes[1];

    float *h1, *el1, *er1, *x1, *h2res, *el2, *er2, *Bcat;
    int *deg, *off, *perm;
    cudaGetSymbolAddress((void**)&h1, g_h1);
    cudaGetSymbolAddress((void**)&el1, g_el1);
    cudaGetSymbolAddress((void**)&er1, g_er1);
    cudaGetSymbolAddress((void**)&x1, g_x1);
    cudaGetSymbolAddress((void**)&h2res, g_h2res);
    cudaGetSymbolAddress((void**)&el2, g_el2);
    cudaGetSymbolAddress((void**)&er2, g_er2);
    cudaGetSymbolAddress((void**)&Bcat, g_Bcat);
    cudaGetSymbolAddress((void**)&deg, g_deg);
    cudaGetSymbolAddress((void**)&off, g_off);
    cudaGetSymbolAddress((void**)&perm, g_perm);

    int eb = (E + 255) / 256;
    int nb = (NN + 255) / 256;
    int wb = (NN * 32 + 255) / 256;   // warp-per-node kernels

    // CSR build
    k_zero_int<<<nb, 256>>>(deg, NN);
    k_hist<<<eb, 256>>>(dst, E, deg);
    k_scan<<<1, 1024>>>(deg, off, NN);
    k_zero_int<<<nb, 256>>>(deg, NN);
    k_scatter<<<eb, 256>>>(dst, E, off, deg, perm);

    // layer 1
    k_sgemm<<<dim3((NN + 63) / 64, F1 / 64), 256>>>(feats, W1, h1, NN, F1, FIN);
    k_attn1<<<wb, 256>>>(h1, al1, ar1, el1, er1);
    k_agg1<<<wb, 256>>>(src, perm, off, h1, el1, er1, feats, b1, x1);

    // layer 2 (h2 and residual projection fused into one GEMM)
    k_concat<<<(FIN * 128 + 255) / 256, 256>>>(W2, rw2, Bcat);
    k_sgemm<<<dim3((NN + 63) / 64, 128 / 64), 256>>>(x1, Bcat, h2res, NN, 128, FIN);
    k_attn2<<<wb, 256>>>(h2res, al2, ar2, el2, er2);
    k_agg2<<<wb, 256>>>(src, perm, off, h2res, el2, er2, b2, out);
}

// round 2
// speedup vs baseline: 1.7641x; 1.7641x over previous
#include <cuda_runtime.h>
#include <math.h>

#define NN   50000
#define FIN  256
#define H1N  8
#define F1   256     // H1*HID
#define NEG  0.2f
#define EMAX 900000

// ---------------- scratch (device globals; no allocation allowed) ----------------
__device__ __align__(256) float g_h1[NN * F1];
__device__ __align__(256) float g_el1[NN * H1N];
__device__ __align__(256) float g_er1[NN * H1N];
__device__ __align__(256) float g_x1[NN * F1];
__device__ __align__(256) float g_h2res[NN * 128];   // [h2 (64) | residual (64)]
__device__ __align__(256) float g_el2[NN];
__device__ __align__(256) float g_er2[NN];
__device__ __align__(256) float g_Bcat[FIN * 128];
__device__ __align__(256) float g_ew1[EMAX * 8];     // exp(e) per edge per head (layer1)
__device__ __align__(256) float g_ew2[EMAX];         // layer2
__device__ int g_deg[NN];
__device__ int g_off[NN + 1];
__device__ int g_us[EMAX];                            // src id in CSR order

// ---------------- CSR build ----------------
__global__ void k_zero_int(int* a, int n) {
    int i = blockIdx.x * blockDim.x + threadIdx.x;
    if (i < n) a[i] = 0;
}

__global__ void k_hist(const int* __restrict__ dst, int E, int* __restrict__ deg) {
    int i = blockIdx.x * blockDim.x + threadIdx.x;
    if (i < E) atomicAdd(&deg[dst[i]], 1);
}

__global__ void k_scan(const int* __restrict__ deg, int* __restrict__ off, int n) {
    __shared__ int wsum[32];
    __shared__ int carry;
    int tid = threadIdx.x, lane = tid & 31, wid = tid >> 5;
    if (tid == 0) carry = 0;
    __syncthreads();
    for (int base = 0; base < n; base += 1024) {
        int i = base + tid;
        int v = (i < n) ? deg[i] : 0;
        int x = v;
        #pragma unroll
        for (int o = 1; o < 32; o <<= 1) {
            int y = __shfl_up_sync(0xffffffffu, x, o);
            if (lane >= o) x += y;
        }
        if (lane == 31) wsum[wid] = x;
        __syncthreads();
        if (wid == 0) {
            int w = wsum[lane];
            #pragma unroll
            for (int o = 1; o < 32; o <<= 1) {
                int y = __shfl_up_sync(0xffffffffu, w, o);
                if (lane >= o) w += y;
            }
            wsum[lane] = w;
        }
        __syncthreads();
        int incl = x + (wid ? wsum[wid - 1] : 0) + carry;
        if (i < n) off[i] = incl - v;
        __syncthreads();
        if (tid == 1023) carry = incl;
        __syncthreads();
    }
    if (tid == 0) off[n] = carry;
}

__global__ void k_scatter(const int* __restrict__ src, const int* __restrict__ dst,
                          int E, const int* __restrict__ off, int* __restrict__ cur,
                          int* __restrict__ us) {
    int i = blockIdx.x * blockDim.x + threadIdx.x;
    if (i < E) {
        int d = dst[i];
        int p = off[d] + atomicAdd(&cur[d], 1);
        us[p] = src[i];
    }
}

// ---------------- TF32 tensor-core GEMM ----------------
// C[M,N] = A[M,K] @ B[K,N], fp32 in/out, tf32 mma with fp32 accumulate.
// BM=128, BN=64, BK=32; 128 threads = 4 warps in 2x2; warp tile 64x32.
__device__ __forceinline__ unsigned f2tf(float x) {
    unsigned u;
    asm("cvt.rna.tf32.f32 %0, %1;" : "=r"(u) : "f"(x));
    return u;
}

__device__ __forceinline__ void mma_tf32(float* d, const unsigned* a, const unsigned* b) {
    asm volatile(
        "mma.sync.aligned.m16n8k8.row.col.f32.tf32.tf32.f32 "
        "{%0,%1,%2,%3}, {%4,%5,%6,%7}, {%8,%9}, {%0,%1,%2,%3};\n"
        : "+f"(d[0]), "+f"(d[1]), "+f"(d[2]), "+f"(d[3])
        : "r"(a[0]), "r"(a[1]), "r"(a[2]), "r"(a[3]), "r"(b[0]), "r"(b[1]));
}

__global__ __launch_bounds__(128)
void k_mma_gemm(const float* __restrict__ A, const float* __restrict__ B,
                float* __restrict__ C, int M, int N, int K) {
    __shared__ unsigned As[128][36];  // padded: bank = (4m + k) % 32, conflict-free frags
    __shared__ unsigned Bs[32][72];   // padded: bank = (8k + n) % 32, conflict-free frags
    int t = threadIdx.x;
    int lane = t & 31;
    int warp = t >> 5;
    int g = lane >> 2, q = lane & 3;
    int warpM = warp & 1, warpN = warp >> 1;
    int bm = blockIdx.x * 128, bn = blockIdx.y * 64;

    float acc[4][4][4] = {};

    for (int kt = 0; kt < K; kt += 32) {
        // A tile: 128x32 = 1024 float4, 8 per thread
        #pragma unroll
        for (int i = 0; i < 8; i++) {
            int idx = t + i * 128;
            int r = idx >> 3, c4 = (idx & 7) * 4;
            float4 v = make_float4(0.f, 0.f, 0.f, 0.f);
            if (bm + r < M)
                v = *(const float4*)&A[(size_t)(bm + r) * K + kt + c4];
            As[r][c4 + 0] = f2tf(v.x);
            As[r][c4 + 1] = f2tf(v.y);
            As[r][c4 + 2] = f2tf(v.z);
            As[r][c4 + 3] = f2tf(v.w);
        }
        // B tile: 32x64 = 512 float4, 4 per thread
        #pragma unroll
        for (int i = 0; i < 4; i++) {
            int idx = t + i * 128;
            int r = idx >> 4, c4 = (idx & 15) * 4;
            float4 v = *(const float4*)&B[(size_t)(kt + r) * N + bn + c4];
            Bs[r][c4 + 0] = f2tf(v.x);
            Bs[r][c4 + 1] = f2tf(v.y);
            Bs[r][c4 + 2] = f2tf(v.z);
            Bs[r][c4 + 3] = f2tf(v.w);
        }
        __syncthreads();

        #pragma unroll
        for (int ks = 0; ks < 4; ks++) {
            int k0 = ks * 8;
            unsigned af[4][4], bf[4][2];
            #pragma unroll
            for (int mt = 0; mt < 4; mt++) {
                int rb = warpM * 64 + mt * 16;
                af[mt][0] = As[rb + g][k0 + q];
                af[mt][1] = As[rb + g + 8][k0 + q];
                af[mt][2] = As[rb + g][k0 + q + 4];
                af[mt][3] = As[rb + g + 8][k0 + q + 4];
            }
            #pragma unroll
            for (int nt = 0; nt < 4; nt++) {
                int cb = warpN * 32 + nt * 8;
                bf[nt][0] = Bs[k0 + q][cb + g];
                bf[nt][1] = Bs[k0 + q + 4][cb + g];
            }
            #pragma unroll
            for (int mt = 0; mt < 4; mt++)
                #pragma unroll
                for (int nt = 0; nt < 4; nt++)
                    mma_tf32(acc[mt][nt], af[mt], bf[nt]);
        }
        __syncthreads();
    }

    // store: c0/c1 at (g, 2q), c2/c3 at (g+8, 2q)
    #pragma unroll
    for (int mt = 0; mt < 4; mt++) {
        int r0 = bm + warpM * 64 + mt * 16 + g;
        #pragma unroll
        for (int nt = 0; nt < 4; nt++) {
            int c = bn + warpN * 32 + nt * 8 + q * 2;
            if (r0 < M)
                *(float2*)&C[(size_t)r0 * N + c] = make_float2(acc[mt][nt][0], acc[mt][nt][1]);
            if (r0 + 8 < M)
                *(float2*)&C[(size_t)(r0 + 8) * N + c] = make_float2(acc[mt][nt][2], acc[mt][nt][3]);
        }
    }
}

// ---------------- attention dot products ----------------
__global__ void k_attn1(const float* __restrict__ h1, const float* __restrict__ al,
                        const float* __restrict__ ar, float* __restrict__ el,
                        float* __restrict__ er) {
    int w = (blockIdx.x * blockDim.x + threadIdx.x) >> 5;
    if (w >= NN) return;
    int lane = threadIdx.x & 31;
    const float* hp = h1 + (size_t)w * F1;
    float se[8], sr[8];
    #pragma unroll
    for (int j = 0; j < 8; j++) {
        float h = hp[lane + 32 * j];
        se[j] = h * al[j * 32 + lane];
        sr[j] = h * ar[j * 32 + lane];
    }
    #pragma unroll
    for (int j = 0; j < 8; j++) {
        #pragma unroll
        for (int o = 16; o; o >>= 1) {
            se[j] += __shfl_xor_sync(0xffffffffu, se[j], o);
            sr[j] += __shfl_xor_sync(0xffffffffu, sr[j], o);
        }
    }
    #pragma unroll
    for (int j = 0; j < 8; j++) {
        if (lane == j) {
            el[w * 8 + j] = se[j];
            er[w * 8 + j] = sr[j];
        }
    }
}

__global__ void k_attn2(const float* __restrict__ h2res, const float* __restrict__ al,
                        const float* __restrict__ ar, float* __restrict__ el,
                        float* __restrict__ er) {
    int w = (blockIdx.x * blockDim.x + threadIdx.x) >> 5;
    if (w >= NN) return;
    int lane = threadIdx.x & 31;
    const float* hp = h2res + (size_t)w * 128;
    float h0 = hp[lane], h1v = hp[lane + 32];
    float a = h0 * al[lane] + h1v * al[lane + 32];
    float b = h0 * ar[lane] + h1v * ar[lane + 32];
    #pragma unroll
    for (int o = 16; o; o >>= 1) {
        a += __shfl_xor_sync(0xffffffffu, a, o);
        b += __shfl_xor_sync(0xffffffffu, b, o);
    }
    if (lane == 0) { el[w] = a; er[w] = b; }
}

// ---------------- layer-1 aggregation (warp per dst node) ----------------
// No max-subtraction: e = el+er is small (~N(0,1.3)); exp cannot overflow.
__global__ void k_agg1(const int* __restrict__ us, const int* __restrict__ off,
                       const float* __restrict__ h1, const float* __restrict__ el,
                       const float* __restrict__ er, const float* __restrict__ feats,
                       const float* __restrict__ bias, float* __restrict__ x1,
                       float* __restrict__ ew) {
    int w = (blockIdx.x * blockDim.x + threadIdx.x) >> 5;
    if (w >= NN) return;
    int lane = threadIdx.x & 31;
    int s0 = off[w], s1 = off[w + 1];

    float4 er0 = *(const float4*)&er[w * 8];
    float4 er1 = *(const float4*)&er[w * 8 + 4];
    float erv[8] = {er0.x, er0.y, er0.z, er0.w, er1.x, er1.y, er1.z, er1.w};

    // pass 1: per-lane exp-sum; store exp(e) per edge-head
    float s[8] = {0.f, 0.f, 0.f, 0.f, 0.f, 0.f, 0.f, 0.f};
    for (int idx = s0 + lane; idx < s1; idx += 32) {
        int u = us[idx];
        float4 e0 = *(const float4*)&el[u * 8];
        float4 e1 = *(const float4*)&el[u * 8 + 4];
        float elv[8] = {e0.x, e0.y, e0.z, e0.w, e1.x, e1.y, e1.z, e1.w};
        float w8[8];
        #pragma unroll
        for (int j = 0; j < 8; j++) {
            float t = elv[j] + erv[j];
            t = t > 0.f ? t : NEG * t;
            float x = __expf(t);
            w8[j] = x;
            s[j] += x;
        }
        *(float4*)&ew[(size_t)idx * 8]     = make_float4(w8[0], w8[1], w8[2], w8[3]);
        *(float4*)&ew[(size_t)idx * 8 + 4] = make_float4(w8[4], w8[5], w8[6], w8[7]);
    }
    #pragma unroll
    for (int j = 0; j < 8; j++)
        #pragma unroll
        for (int o = 16; o; o >>= 1)
            s[j] += __shfl_xor_sync(0xffffffffu, s[j], o);

    float is_l = 0.f;
    if (lane < 8) is_l = 1.f / s[lane];

    // pass 2: weighted gather (feature f = lane + 32*j -> head j)
    float acc[8] = {0.f, 0.f, 0.f, 0.f, 0.f, 0.f, 0.f, 0.f};
    for (int i = s0; i < s1; i++) {
        int u = us[i];
        float alpha = 0.f;
        if (lane < 8) alpha = ew[(size_t)i * 8 + lane] * is_l;
        const float* hu = h1 + (size_t)u * F1;
        #pragma unroll
        for (int j = 0; j < 8; j++) {
            float a = __shfl_sync(0xffffffffu, alpha, j);
            acc[j] += hu[lane + 32 * j] * a;
        }
    }

    #pragma unroll
    for (int j = 0; j < 8; j++) {
        int f = lane + 32 * j;
        float r = acc[j] + feats[(size_t)w * FIN + f] + bias[f];
        x1[(size_t)w * F1 + f] = r > 0.f ? r : expm1f(r);
    }
}

// ---------------- concat [W2 | res_W2] ----------------
__global__ void k_concat(const float* __restrict__ W2, const float* __restrict__ rw,
                         float* __restrict__ Bcat) {
    int i = blockIdx.x * blockDim.x + threadIdx.x;
    if (i < FIN * 128) {
        int k = i >> 7, c = i & 127;
        Bcat[i] = (c < 64) ? W2[k * 64 + c] : rw[k * 64 + (c - 64)];
    }
}

// ---------------- layer-2 aggregation ----------------
__global__ void k_agg2(const int* __restrict__ us, const int* __restrict__ off,
                       const float* __restrict__ h2res, const float* __restrict__ el,
                       const float* __restrict__ er, const float* __restrict__ bias,
                       float* __restrict__ out, float* __restrict__ ew) {
    int w = (blockIdx.x * blockDim.x + threadIdx.x) >> 5;
    if (w >= NN) return;
    int lane = threadIdx.x & 31;
    int s0 = off[w], s1 = off[w + 1];
    float erv = er[w];

    float s = 0.f;
    for (int idx = s0 + lane; idx < s1; idx += 32) {
        int u = us[idx];
        float t = el[u] + erv;
        t = t > 0.f ? t : NEG * t;
        float x = __expf(t);
        ew[idx] = x;
        s += x;
    }
    #pragma unroll
    for (int o = 16; o; o >>= 1)
        s += __shfl_xor_sync(0xffffffffu, s, o);
    float is = 1.f / s;

    float a0 = 0.f, a1 = 0.f;
    for (int i = s0; i < s1; i++) {
        float alpha = ew[i] * is;
        const float* hu = h2res + (size_t)us[i] * 128;
        a0 += hu[lane] * alpha;
        a1 += hu[lane + 32] * alpha;
    }
    const float* rv = h2res + (size_t)w * 128 + 64;
    out[(size_t)w * 64 + lane]      = a0 + rv[lane]      + bias[lane];
    out[(size_t)w * 64 + lane + 32] = a1 + rv[lane + 32] + bias[lane + 32];
}

// ---------------- launch ----------------
extern "C" void kernel_launch(void* const* d_in, const int* in_sizes, int n_in,
                              void* d_out, int out_size) {
    const float* feats = (const float*)d_in[0];
    const int*   src   = (const int*)d_in[1];
    const int*   dst   = (const int*)d_in[2];
    const float* W1    = (const float*)d_in[3];
    const float* al1   = (const float*)d_in[4];
    const float* ar1   = (const float*)d_in[5];
    const float* b1    = (const float*)d_in[6];
    const float* W2    = (const float*)d_in[7];
    const float* al2   = (const float*)d_in[8];
    const float* ar2   = (const float*)d_in[9];
    const float* b2    = (const float*)d_in[10];
    const float* rw2   = (const float*)d_in[11];
    float* out = (float*)d_out;
    int E = in_sizes[1];

    float *h1, *el1, *er1, *x1, *h2res, *el2, *er2, *Bcat, *ew1, *ew2;
    int *deg, *off, *us;
    cudaGetSymbolAddress((void**)&h1, g_h1);
    cudaGetSymbolAddress((void**)&el1, g_el1);
    cudaGetSymbolAddress((void**)&er1, g_er1);
    cudaGetSymbolAddress((void**)&x1, g_x1);
    cudaGetSymbolAddress((void**)&h2res, g_h2res);
    cudaGetSymbolAddress((void**)&el2, g_el2);
    cudaGetSymbolAddress((void**)&er2, g_er2);
    cudaGetSymbolAddress((void**)&Bcat, g_Bcat);
    cudaGetSymbolAddress((void**)&ew1, g_ew1);
    cudaGetSymbolAddress((void**)&ew2, g_ew2);
    cudaGetSymbolAddress((void**)&deg, g_deg);
    cudaGetSymbolAddress((void**)&off, g_off);
    cudaGetSymbolAddress((void**)&us, g_us);

    int eb = (E + 255) / 256;
    int nb = (NN + 255) / 256;
    int wb = (NN * 32 + 255) / 256;

    // CSR build
    k_zero_int<<<nb, 256>>>(deg, NN);
    k_hist<<<eb, 256>>>(dst, E, deg);
    k_scan<<<1, 1024>>>(deg, off, NN);
    k_zero_int<<<nb, 256>>>(deg, NN);
    k_scatter<<<eb, 256>>>(src, dst, E, off, deg, us);

    // layer 1
    k_mma_gemm<<<dim3((NN + 127) / 128, F1 / 64), 128>>>(feats, W1, h1, NN, F1, FIN);
    k_attn1<<<wb, 256>>>(h1, al1, ar1, el1, er1);
    k_agg1<<<wb, 256>>>(us, off, h1, el1, er1, feats, b1, x1, ew1);

    // layer 2 (h2 + residual fused in one GEMM)
    k_concat<<<(FIN * 128 + 255) / 256, 256>>>(W2, rw2, Bcat);
    k_mma_gemm<<<dim3((NN + 127) / 128, 128 / 64), 128>>>(x1, Bcat, h2res, NN, 128, FIN);
    k_attn2<<<wb, 256>>>(h2res, al2, ar2, el2, er2);
    k_agg2<<<wb, 256>>>(us, off, h2res, el2, er2, b2, out, ew2);
}

// round 3
// speedup vs baseline: 2.0774x; 1.1776x over previous
#include <cuda_runtime.h>
#include <math.h>

#define NN   50000
#define FIN  256
#define H1N  8
#define F1   256
#define NEG  0.2f
#define EMAX 900000
#define FULL 0xffffffffu

// ---------------- scratch ----------------
__device__ __align__(256) float g_h1[NN * F1];
__device__ __align__(256) float g_el1[NN * H1N];
__device__ __align__(256) float g_er1[NN * H1N];
__device__ __align__(256) float g_x1[NN * F1];
__device__ __align__(256) float g_h2res[NN * 128];   // [h2 (64) | residual (64)]
__device__ __align__(256) float g_el2[NN];
__device__ __align__(256) float g_er2[NN];
__device__ __align__(256) float g_Bcat[FIN * 128];
__device__ int g_deg[NN];
__device__ int g_off[NN + 1];
__device__ int g_us[EMAX];

// ---------------- CSR build ----------------
__global__ void k_zero_int(int* a, int n) {
    int i = blockIdx.x * blockDim.x + threadIdx.x;
    if (i < n) a[i] = 0;
}

__global__ void k_hist(const int* __restrict__ dst, int E, int* __restrict__ deg) {
    int i = blockIdx.x * blockDim.x + threadIdx.x;
    if (i < E) atomicAdd(&deg[dst[i]], 1);
}

__global__ void k_scan(const int* __restrict__ deg, int* __restrict__ off, int n) {
    __shared__ int wsum[32];
    __shared__ int carry;
    int tid = threadIdx.x, lane = tid & 31, wid = tid >> 5;
    if (tid == 0) carry = 0;
    __syncthreads();
    for (int base = 0; base < n; base += 1024) {
        int i = base + tid;
        int v = (i < n) ? deg[i] : 0;
        int x = v;
        #pragma unroll
        for (int o = 1; o < 32; o <<= 1) {
            int y = __shfl_up_sync(FULL, x, o);
            if (lane >= o) x += y;
        }
        if (lane == 31) wsum[wid] = x;
        __syncthreads();
        if (wid == 0) {
            int w = wsum[lane];
            #pragma unroll
            for (int o = 1; o < 32; o <<= 1) {
                int y = __shfl_up_sync(FULL, w, o);
                if (lane >= o) w += y;
            }
            wsum[lane] = w;
        }
        __syncthreads();
        int incl = x + (wid ? wsum[wid - 1] : 0) + carry;
        if (i < n) off[i] = incl - v;
        __syncthreads();
        if (tid == 1023) carry = incl;
        __syncthreads();
    }
    if (tid == 0) off[n] = carry;
}

__global__ void k_scatter(const int* __restrict__ src, const int* __restrict__ dst,
                          int E, const int* __restrict__ off, int* __restrict__ cur,
                          int* __restrict__ us) {
    int i = blockIdx.x * blockDim.x + threadIdx.x;
    if (i < E) {
        int d = dst[i];
        int p = off[d] + atomicAdd(&cur[d], 1);
        us[p] = src[i];
    }
}

// ---------------- TF32 tensor-core GEMM, register-staged pipeline ----------------
// C[M,N] = A[M,K] @ B[K,N]. BM=128, BN=64, BK=32, 256 threads (8 warps, 4x2).
__device__ __forceinline__ unsigned f2tf(float x) {
    unsigned u;
    asm("cvt.rna.tf32.f32 %0, %1;" : "=r"(u) : "f"(x));
    return u;
}

__device__ __forceinline__ void mma_tf32(float* d, const unsigned* a, const unsigned* b) {
    asm volatile(
        "mma.sync.aligned.m16n8k8.row.col.f32.tf32.tf32.f32 "
        "{%0,%1,%2,%3}, {%4,%5,%6,%7}, {%8,%9}, {%0,%1,%2,%3};\n"
        : "+f"(d[0]), "+f"(d[1]), "+f"(d[2]), "+f"(d[3])
        : "r"(a[0]), "r"(a[1]), "r"(a[2]), "r"(a[3]), "r"(b[0]), "r"(b[1]));
}

__global__ __launch_bounds__(256)
void k_mma_gemm(const float* __restrict__ A, const float* __restrict__ B,
                float* __restrict__ C, int M, int N, int K) {
    __shared__ unsigned As[128][36];
    __shared__ unsigned Bs[32][72];
    int t = threadIdx.x;
    int lane = t & 31;
    int warp = t >> 5;
    int g = lane >> 2, q = lane & 3;
    int warpM = warp & 3, warpN = warp >> 2;   // 4x2 warps, warp tile 32x32
    int bm = blockIdx.x * 128, bn = blockIdx.y * 64;

    int ar = t >> 1, ac4 = (t & 1) * 4;        // per-thread A: rows t>>1? no:
    // A tile 128x32 = 1024 float4 -> 4 per thread
    // B tile 32x64  =  512 float4 -> 2 per thread
    float4 avs[4], bvs[2];

    float acc[2][4][4] = {};
    (void)ar; (void)ac4;

    // ---- load k-tile kt into regs ----
    auto loadA = [&](int kt, float4* av) {
        #pragma unroll
        for (int i = 0; i < 4; i++) {
            int idx = t + i * 256;
            int r = idx >> 3, c4 = (idx & 7) * 4;
            float4 v = make_float4(0.f, 0.f, 0.f, 0.f);
            if (bm + r < M)
                v = *(const float4*)&A[(size_t)(bm + r) * K + kt + c4];
            av[i] = v;
        }
    };
    auto loadB = [&](int kt, float4* bv) {
        #pragma unroll
        for (int i = 0; i < 2; i++) {
            int idx = t + i * 256;
            int r = idx >> 4, c4 = (idx & 15) * 4;
            bv[i] = *(const float4*)&B[(size_t)(kt + r) * N + bn + c4];
        }
    };
    auto stage = [&](const float4* av, const float4* bv) {
        #pragma unroll
        for (int i = 0; i < 4; i++) {
            int idx = t + i * 256;
            int r = idx >> 3, c4 = (idx & 7) * 4;
            As[r][c4 + 0] = f2tf(av[i].x);
            As[r][c4 + 1] = f2tf(av[i].y);
            As[r][c4 + 2] = f2tf(av[i].z);
            As[r][c4 + 3] = f2tf(av[i].w);
        }
        #pragma unroll
        for (int i = 0; i < 2; i++) {
            int idx = t + i * 256;
            int r = idx >> 4, c4 = (idx & 15) * 4;
            Bs[r][c4 + 0] = f2tf(bv[i].x);
            Bs[r][c4 + 1] = f2tf(bv[i].y);
            Bs[r][c4 + 2] = f2tf(bv[i].z);
            Bs[r][c4 + 3] = f2tf(bv[i].w);
        }
    };

    loadA(0, avs);
    loadB(0, bvs);
    stage(avs, bvs);
    __syncthreads();

    for (int kt = 0; kt < K; kt += 32) {
        bool nxt = (kt + 32) < K;
        if (nxt) { loadA(kt + 32, avs); loadB(kt + 32, bvs); }

        #pragma unroll
        for (int ks = 0; ks < 4; ks++) {
            int k0 = ks * 8;
            unsigned af[2][4], bf[4][2];
            #pragma unroll
            for (int mt = 0; mt < 2; mt++) {
                int rb = warpM * 32 + mt * 16;
                af[mt][0] = As[rb + g][k0 + q];
                af[mt][1] = As[rb + g + 8][k0 + q];
                af[mt][2] = As[rb + g][k0 + q + 4];
                af[mt][3] = As[rb + g + 8][k0 + q + 4];
            }
            #pragma unroll
            for (int nt = 0; nt < 4; nt++) {
                int cb = warpN * 32 + nt * 8;
                bf[nt][0] = Bs[k0 + q][cb + g];
                bf[nt][1] = Bs[k0 + q + 4][cb + g];
            }
            #pragma unroll
            for (int mt = 0; mt < 2; mt++)
                #pragma unroll
                for (int nt = 0; nt < 4; nt++)
                    mma_tf32(acc[mt][nt], af[mt], bf[nt]);
        }
        if (nxt) {
            __syncthreads();
            stage(avs, bvs);
            __syncthreads();
        }
    }

    #pragma unroll
    for (int mt = 0; mt < 2; mt++) {
        int r0 = bm + warpM * 32 + mt * 16 + g;
        #pragma unroll
        for (int nt = 0; nt < 4; nt++) {
            int c = bn + warpN * 32 + nt * 8 + q * 2;
            if (r0 < M)
                *(float2*)&C[(size_t)r0 * N + c] = make_float2(acc[mt][nt][0], acc[mt][nt][1]);
            if (r0 + 8 < M)
                *(float2*)&C[(size_t)(r0 + 8) * N + c] = make_float2(acc[mt][nt][2], acc[mt][nt][3]);
        }
    }
}

// ---------------- attention dots (layer 1), vectorized ----------------
__global__ void k_attn1(const float* __restrict__ h1, const float* __restrict__ al,
                        const float* __restrict__ ar, float* __restrict__ el,
                        float* __restrict__ er) {
    int w = (blockIdx.x * blockDim.x + threadIdx.x) >> 5;
    if (w >= NN) return;
    int lane = threadIdx.x & 31;
    const float4* hp = (const float4*)(h1 + (size_t)w * F1);
    const float4* al4 = (const float4*)al;
    const float4* ar4 = (const float4*)ar;
    float4 h0 = hp[lane], h1v = hp[lane + 32];
    float4 a0 = al4[lane], a1 = al4[lane + 32];
    float4 r0 = ar4[lane], r1 = ar4[lane + 32];
    float elA = h0.x * a0.x + h0.y * a0.y + h0.z * a0.z + h0.w * a0.w;
    float elB = h1v.x * a1.x + h1v.y * a1.y + h1v.z * a1.z + h1v.w * a1.w;
    float erA = h0.x * r0.x + h0.y * r0.y + h0.z * r0.z + h0.w * r0.w;
    float erB = h1v.x * r1.x + h1v.y * r1.y + h1v.z * r1.z + h1v.w * r1.w;
    #pragma unroll
    for (int o = 4; o; o >>= 1) {
        elA += __shfl_xor_sync(FULL, elA, o);
        elB += __shfl_xor_sync(FULL, elB, o);
        erA += __shfl_xor_sync(FULL, erA, o);
        erB += __shfl_xor_sync(FULL, erB, o);
    }
    if ((lane & 7) == 0) {
        int h = lane >> 3;
        el[w * 8 + h]     = elA;
        el[w * 8 + 4 + h] = elB;
        er[w * 8 + h]     = erA;
        er[w * 8 + 4 + h] = erB;
    }
}

__global__ void k_attn2(const float* __restrict__ h2res, const float* __restrict__ al,
                        const float* __restrict__ ar, float* __restrict__ el,
                        float* __restrict__ er) {
    int w = (blockIdx.x * blockDim.x + threadIdx.x) >> 5;
    if (w >= NN) return;
    int lane = threadIdx.x & 31;
    const float2* hp = (const float2*)(h2res + (size_t)w * 128);
    float2 h = hp[lane];
    float2 av = ((const float2*)al)[lane];
    float2 rv = ((const float2*)ar)[lane];
    float a = h.x * av.x + h.y * av.y;
    float b = h.x * rv.x + h.y * rv.y;
    #pragma unroll
    for (int o = 16; o; o >>= 1) {
        a += __shfl_xor_sync(FULL, a, o);
        b += __shfl_xor_sync(FULL, b, o);
    }
    if (lane == 0) { el[w] = a; er[w] = b; }
}

// ---------------- layer-1 aggregation: single-pass unnormalized softmax ----------------
// rst = (sum_i exp(e_i) * h_i) / sum_i exp(e_i)   (no max-sub needed; e is small)
__global__ void k_agg1(const int* __restrict__ us, const int* __restrict__ off,
                       const float* __restrict__ h1, const float* __restrict__ el,
                       const float* __restrict__ er, const float* __restrict__ feats,
                       const float* __restrict__ bias, float* __restrict__ x1) {
    int w = (blockIdx.x * blockDim.x + threadIdx.x) >> 5;
    if (w >= NN) return;
    int lane = threadIdx.x & 31;
    int s0 = off[w], s1 = off[w + 1];
    int hA = lane >> 3, hB = 4 + (lane >> 3);

    float er_l = (lane < 8) ? er[w * 8 + lane] : 0.f;
    float s_l = 0.f;
    float4 acc0 = make_float4(0.f, 0.f, 0.f, 0.f);
    float4 acc1 = make_float4(0.f, 0.f, 0.f, 0.f);

    int u = (s0 < s1) ? us[s0] : 0;
    float ep = (lane < 8 && s0 < s1) ? el[u * 8 + lane] : 0.f;

    for (int i = s0; i < s1; i++) {
        int un = 0; float epn = 0.f;
        if (i + 1 < s1) {
            un = us[i + 1];
            if (lane < 8) epn = el[un * 8 + lane];
        }
        float tt = ep + er_l;
        tt = tt > 0.f ? tt : NEG * tt;
        float ewl = __expf(tt);
        s_l += ewl;
        float aA = __shfl_sync(FULL, ewl, hA);
        float aB = __shfl_sync(FULL, ewl, hB);
        const float4* hu = (const float4*)(h1 + (size_t)u * F1);
        float4 b0 = hu[lane], b1 = hu[lane + 32];
        acc0.x += b0.x * aA; acc0.y += b0.y * aA; acc0.z += b0.z * aA; acc0.w += b0.w * aA;
        acc1.x += b1.x * aB; acc1.y += b1.y * aB; acc1.z += b1.z * aB; acc1.w += b1.w * aB;
        u = un; ep = epn;
    }

    float is_l = (lane < 8) ? 1.f / s_l : 0.f;
    float isA = __shfl_sync(FULL, is_l, hA);
    float isB = __shfl_sync(FULL, is_l, hB);

    const float4* fp = (const float4*)(feats + (size_t)w * FIN);
    const float4* bp = (const float4*)bias;
    float4 f0 = fp[lane], f1 = fp[lane + 32];
    float4 bA = bp[lane], bB = bp[lane + 32];
    float4 o0, o1;
    o0.x = acc0.x * isA + f0.x + bA.x;  o0.y = acc0.y * isA + f0.y + bA.y;
    o0.z = acc0.z * isA + f0.z + bA.z;  o0.w = acc0.w * isA + f0.w + bA.w;
    o1.x = acc1.x * isB + f1.x + bB.x;  o1.y = acc1.y * isB + f1.y + bB.y;
    o1.z = acc1.z * isB + f1.z + bB.z;  o1.w = acc1.w * isB + f1.w + bB.w;
    o0.x = o0.x > 0.f ? o0.x : expm1f(o0.x);
    o0.y = o0.y > 0.f ? o0.y : expm1f(o0.y);
    o0.z = o0.z > 0.f ? o0.z : expm1f(o0.z);
    o0.w = o0.w > 0.f ? o0.w : expm1f(o0.w);
    o1.x = o1.x > 0.f ? o1.x : expm1f(o1.x);
    o1.y = o1.y > 0.f ? o1.y : expm1f(o1.y);
    o1.z = o1.z > 0.f ? o1.z : expm1f(o1.z);
    o1.w = o1.w > 0.f ? o1.w : expm1f(o1.w);
    float4* xp = (float4*)(x1 + (size_t)w * F1);
    xp[lane] = o0;
    xp[lane + 32] = o1;
}

// ---------------- concat [W2 | res_W2] ----------------
__global__ void k_concat(const float* __restrict__ W2, const float* __restrict__ rw,
                         float* __restrict__ Bcat) {
    int i = blockIdx.x * blockDim.x + threadIdx.x;
    if (i < FIN * 128) {
        int k = i >> 7, c = i & 127;
        Bcat[i] = (c < 64) ? W2[k * 64 + c] : rw[k * 64 + (c - 64)];
    }
}

// ---------------- layer-2 aggregation: single-pass ----------------
__global__ void k_agg2(const int* __restrict__ us, const int* __restrict__ off,
                       const float* __restrict__ h2res, const float* __restrict__ el,
                       const float* __restrict__ er, const float* __restrict__ bias,
                       float* __restrict__ out) {
    int w = (blockIdx.x * blockDim.x + threadIdx.x) >> 5;
    if (w >= NN) return;
    int lane = threadIdx.x & 31;
    int s0 = off[w], s1 = off[w + 1];
    float erv = er[w];
    float s = 0.f;
    float2 acc = make_float2(0.f, 0.f);

    int u = (s0 < s1) ? us[s0] : 0;
    float ep = (s0 < s1) ? el[u] : 0.f;

    for (int i = s0; i < s1; i++) {
        int un = 0; float epn = 0.f;
        if (i + 1 < s1) { un = us[i + 1]; epn = el[un]; }
        float tt = ep + erv;
        tt = tt > 0.f ? tt : NEG * tt;
        float e = __expf(tt);
        s += e;
        float2 b = *(const float2*)&h2res[(size_t)u * 128 + 2 * lane];
        acc.x += b.x * e;
        acc.y += b.y * e;
        u = un; ep = epn;
    }
    float is = 1.f / s;
    float2 rv = *(const float2*)&h2res[(size_t)w * 128 + 64 + 2 * lane];
    float2 bv = *(const float2*)&bias[2 * lane];
    float2 o;
    o.x = acc.x * is + rv.x + bv.x;
    o.y = acc.y * is + rv.y + bv.y;
    *(float2*)&out[(size_t)w * 64 + 2 * lane] = o;
}

// ---------------- launch ----------------
extern "C" void kernel_launch(void* const* d_in, const int* in_sizes, int n_in,
                              void* d_out, int out_size) {
    const float* feats = (const float*)d_in[0];
    const int*   src   = (const int*)d_in[1];
    const int*   dst   = (const int*)d_in[2];
    const float* W1    = (const float*)d_in[3];
    const float* al1   = (const float*)d_in[4];
    const float* ar1   = (const float*)d_in[5];
    const float* b1    = (const float*)d_in[6];
    const float* W2    = (const float*)d_in[7];
    const float* al2   = (const float*)d_in[8];
    const float* ar2   = (const float*)d_in[9];
    const float* b2    = (const float*)d_in[10];
    const float* rw2   = (const float*)d_in[11];
    float* out = (float*)d_out;
    int E = in_sizes[1];

    float *h1, *el1, *er1, *x1, *h2res, *el2, *er2, *Bcat;
    int *deg, *off, *us;
    cudaGetSymbolAddress((void**)&h1, g_h1);
    cudaGetSymbolAddress((void**)&el1, g_el1);
    cudaGetSymbolAddress((void**)&er1, g_er1);
    cudaGetSymbolAddress((void**)&x1, g_x1);
    cudaGetSymbolAddress((void**)&h2res, g_h2res);
    cudaGetSymbolAddress((void**)&el2, g_el2);
    cudaGetSymbolAddress((void**)&er2, g_er2);
    cudaGetSymbolAddress((void**)&Bcat, g_Bcat);
    cudaGetSymbolAddress((void**)&deg, g_deg);
    cudaGetSymbolAddress((void**)&off, g_off);
    cudaGetSymbolAddress((void**)&us, g_us);

    // lazily-created side stream + fork/join events (created once, outside capture)
    static cudaStream_t side = nullptr;
    static cudaEvent_t evFork = nullptr, evJoin = nullptr;
    if (!side) {
        cudaStreamCreateWithFlags(&side, cudaStreamNonBlocking);
        cudaEventCreateWithFlags(&evFork, cudaEventDisableTiming);
        cudaEventCreateWithFlags(&evJoin, cudaEventDisableTiming);
    }

    int eb = (E + 255) / 256;
    int nb = (NN + 255) / 256;
    int wb = (NN * 32 + 255) / 256;

    // fork: CSR build + weight concat on side stream, concurrent with GEMM1/attn1
    cudaEventRecord(evFork, 0);
    cudaStreamWaitEvent(side, evFork, 0);
    k_zero_int<<<nb, 256, 0, side>>>(deg, NN);
    k_hist<<<eb, 256, 0, side>>>(dst, E, deg);
    k_scan<<<1, 1024, 0, side>>>(deg, off, NN);
    k_zero_int<<<nb, 256, 0, side>>>(deg, NN);
    k_scatter<<<eb, 256, 0, side>>>(src, dst, E, off, deg, us);
    k_concat<<<(FIN * 128 + 255) / 256, 256, 0, side>>>(W2, rw2, Bcat);
    cudaEventRecord(evJoin, side);

    // main stream: layer-1 dense part
    k_mma_gemm<<<dim3((NN + 127) / 128, F1 / 64), 256>>>(feats, W1, h1, NN, F1, FIN);
    k_attn1<<<wb, 256>>>(h1, al1, ar1, el1, er1);

    // join before sparse aggregation
    cudaStreamWaitEvent(0, evJoin, 0);
    k_agg1<<<wb, 256>>>(us, off, h1, el1, er1, feats, b1, x1);

    // layer 2
    k_mma_gemm<<<dim3((NN + 127) / 128, 128 / 64), 256>>>(x1, Bcat, h2res, NN, 128, FIN);
    k_attn2<<<wb, 256>>>(h2res, al2, ar2, el2, er2);
    k_agg2<<<wb, 256>>>(us, off, h2res, el2, er2, b2, out);
}

// round 5
// speedup vs baseline: 2.1213x; 1.0211x over previous
#include <cuda_runtime.h>
#include <math.h>

#define NN   50000
#define FIN  256
#define H1N  8
#define F1   256
#define NEG  0.2f
#define EMAX 900000
#define FULL 0xffffffffu

// ---------------- scratch ----------------
__device__ __align__(256) float g_h1[NN * F1];
__device__ __align__(256) float g_el1[NN * H1N];
__device__ __align__(256) float g_er1[NN * H1N];
__device__ __align__(256) float g_x1[NN * F1];
__device__ __align__(256) float g_h2res[NN * 128];   // [h2 (64) | residual (64)]
__device__ __align__(256) float g_el2[NN];
__device__ __align__(256) float g_er2[NN];
__device__ __align__(256) float g_Bcat[FIN * 128];
__device__ int g_deg[NN];
__device__ int g_off[NN + 1];
__device__ int g_us[EMAX];

// ---------------- CSR build ----------------
__global__ void k_hist(const int* __restrict__ dst, int E, int* __restrict__ deg) {
    int i = blockIdx.x * blockDim.x + threadIdx.x;
    if (i < E) atomicAdd(&deg[dst[i]], 1);
}

__global__ void k_scan(const int* __restrict__ deg, int* __restrict__ off, int n) {
    __shared__ int wsum[32];
    __shared__ int carry;
    int tid = threadIdx.x, lane = tid & 31, wid = tid >> 5;
    if (tid == 0) carry = 0;
    __syncthreads();
    for (int base = 0; base < n; base += 1024) {
        int i = base + tid;
        int v = (i < n) ? deg[i] : 0;
        int x = v;
        #pragma unroll
        for (int o = 1; o < 32; o <<= 1) {
            int y = __shfl_up_sync(FULL, x, o);
            if (lane >= o) x += y;
        }
        if (lane == 31) wsum[wid] = x;
        __syncthreads();
        if (wid == 0) {
            int w = wsum[lane];
            #pragma unroll
            for (int o = 1; o < 32; o <<= 1) {
                int y = __shfl_up_sync(FULL, w, o);
                if (lane >= o) w += y;
            }
            wsum[lane] = w;
        }
        __syncthreads();
        int incl = x + (wid ? wsum[wid - 1] : 0) + carry;
        if (i < n) off[i] = incl - v;
        __syncthreads();
        if (tid == 1023) carry = incl;
        __syncthreads();
    }
    if (tid == 0) off[n] = carry;
}

__global__ void k_scatter(const int* __restrict__ src, const int* __restrict__ dst,
                          int E, const int* __restrict__ off, int* __restrict__ cur,
                          int* __restrict__ us) {
    int i = blockIdx.x * blockDim.x + threadIdx.x;
    if (i < E) {
        int d = dst[i];
        int p = off[d] + atomicAdd(&cur[d], 1);
        us[p] = src[i];
    }
}

// ---------------- TF32 tensor-core GEMM, register-staged pipeline ----------------
__device__ __forceinline__ unsigned f2tf(float x) {
    unsigned u;
    asm("cvt.rna.tf32.f32 %0, %1;" : "=r"(u) : "f"(x));
    return u;
}

__device__ __forceinline__ void mma_tf32(float* d, const unsigned* a, const unsigned* b) {
    asm volatile(
        "mma.sync.aligned.m16n8k8.row.col.f32.tf32.tf32.f32 "
        "{%0,%1,%2,%3}, {%4,%5,%6,%7}, {%8,%9}, {%0,%1,%2,%3};\n"
        : "+f"(d[0]), "+f"(d[1]), "+f"(d[2]), "+f"(d[3])
        : "r"(a[0]), "r"(a[1]), "r"(a[2]), "r"(a[3]), "r"(b[0]), "r"(b[1]));
}

__global__ __launch_bounds__(256)
void k_mma_gemm(const float* __restrict__ A, const float* __restrict__ B,
                float* __restrict__ C, int M, int N, int K) {
    __shared__ unsigned As[128][36];
    __shared__ unsigned Bs[32][72];
    int t = threadIdx.x;
    int lane = t & 31;
    int warp = t >> 5;
    int g = lane >> 2, q = lane & 3;
    int warpM = warp & 3, warpN = warp >> 2;
    int bm = blockIdx.x * 128, bn = blockIdx.y * 64;

    float4 avs[4], bvs[2];
    float acc[2][4][4] = {};

    auto loadA = [&](int kt, float4* av) {
        #pragma unroll
        for (int i = 0; i < 4; i++) {
            int idx = t + i * 256;
            int r = idx >> 3, c4 = (idx & 7) * 4;
            float4 v = make_float4(0.f, 0.f, 0.f, 0.f);
            if (bm + r < M)
                v = *(const float4*)&A[(size_t)(bm + r) * K + kt + c4];
            av[i] = v;
        }
    };
    auto loadB = [&](int kt, float4* bv) {
        #pragma unroll
        for (int i = 0; i < 2; i++) {
            int idx = t + i * 256;
            int r = idx >> 4, c4 = (idx & 15) * 4;
            bv[i] = *(const float4*)&B[(size_t)(kt + r) * N + bn + c4];
        }
    };
    auto stage = [&](const float4* av, const float4* bv) {
        #pragma unroll
        for (int i = 0; i < 4; i++) {
            int idx = t + i * 256;
            int r = idx >> 3, c4 = (idx & 7) * 4;
            As[r][c4 + 0] = f2tf(av[i].x);
            As[r][c4 + 1] = f2tf(av[i].y);
            As[r][c4 + 2] = f2tf(av[i].z);
            As[r][c4 + 3] = f2tf(av[i].w);
        }
        #pragma unroll
        for (int i = 0; i < 2; i++) {
            int idx = t + i * 256;
            int r = idx >> 4, c4 = (idx & 15) * 4;
            Bs[r][c4 + 0] = f2tf(bv[i].x);
            Bs[r][c4 + 1] = f2tf(bv[i].y);
            Bs[r][c4 + 2] = f2tf(bv[i].z);
            Bs[r][c4 + 3] = f2tf(bv[i].w);
        }
    };

    loadA(0, avs);
    loadB(0, bvs);
    stage(avs, bvs);
    __syncthreads();

    for (int kt = 0; kt < K; kt += 32) {
        bool nxt = (kt + 32) < K;
        if (nxt) { loadA(kt + 32, avs); loadB(kt + 32, bvs); }

        #pragma unroll
        for (int ks = 0; ks < 4; ks++) {
            int k0 = ks * 8;
            unsigned af[2][4], bf[4][2];
            #pragma unroll
            for (int mt = 0; mt < 2; mt++) {
                int rb = warpM * 32 + mt * 16;
                af[mt][0] = As[rb + g][k0 + q];
                af[mt][1] = As[rb + g + 8][k0 + q];
                af[mt][2] = As[rb + g][k0 + q + 4];
                af[mt][3] = As[rb + g + 8][k0 + q + 4];
            }
            #pragma unroll
            for (int nt = 0; nt < 4; nt++) {
                int cb = warpN * 32 + nt * 8;
                bf[nt][0] = Bs[k0 + q][cb + g];
                bf[nt][1] = Bs[k0 + q + 4][cb + g];
            }
            #pragma unroll
            for (int mt = 0; mt < 2; mt++)
                #pragma unroll
                for (int nt = 0; nt < 4; nt++)
                    mma_tf32(acc[mt][nt], af[mt], bf[nt]);
        }
        if (nxt) {
            __syncthreads();
            stage(avs, bvs);
            __syncthreads();
        }
    }

    #pragma unroll
    for (int mt = 0; mt < 2; mt++) {
        int r0 = bm + warpM * 32 + mt * 16 + g;
        #pragma unroll
        for (int nt = 0; nt < 4; nt++) {
            int c = bn + warpN * 32 + nt * 8 + q * 2;
            if (r0 < M)
                *(float2*)&C[(size_t)r0 * N + c] = make_float2(acc[mt][nt][0], acc[mt][nt][1]);
            if (r0 + 8 < M)
                *(float2*)&C[(size_t)(r0 + 8) * N + c] = make_float2(acc[mt][nt][2], acc[mt][nt][3]);
        }
    }
}

// ---------------- attention dots ----------------
__global__ void k_attn1(const float* __restrict__ h1, const float* __restrict__ al,
                        const float* __restrict__ ar, float* __restrict__ el,
                        float* __restrict__ er) {
    int w = (blockIdx.x * blockDim.x + threadIdx.x) >> 5;
    if (w >= NN) return;
    int lane = threadIdx.x & 31;
    const float4* hp = (const float4*)(h1 + (size_t)w * F1);
    const float4* al4 = (const float4*)al;
    const float4* ar4 = (const float4*)ar;
    float4 h0 = hp[lane], h1v = hp[lane + 32];
    float4 a0 = al4[lane], a1 = al4[lane + 32];
    float4 r0 = ar4[lane], r1 = ar4[lane + 32];
    float elA = h0.x * a0.x + h0.y * a0.y + h0.z * a0.z + h0.w * a0.w;
    float elB = h1v.x * a1.x + h1v.y * a1.y + h1v.z * a1.z + h1v.w * a1.w;
    float erA = h0.x * r0.x + h0.y * r0.y + h0.z * r0.z + h0.w * r0.w;
    float erB = h1v.x * r1.x + h1v.y * r1.y + h1v.z * r1.z + h1v.w * r1.w;
    #pragma unroll
    for (int o = 4; o; o >>= 1) {
        elA += __shfl_xor_sync(FULL, elA, o);
        elB += __shfl_xor_sync(FULL, elB, o);
        erA += __shfl_xor_sync(FULL, erA, o);
        erB += __shfl_xor_sync(FULL, erB, o);
    }
    if ((lane & 7) == 0) {
        int h = lane >> 3;
        el[w * 8 + h]     = elA;
        el[w * 8 + 4 + h] = elB;
        er[w * 8 + h]     = erA;
        er[w * 8 + 4 + h] = erB;
    }
}

__global__ void k_attn2(const float* __restrict__ h2res, const float* __restrict__ al,
                        const float* __restrict__ ar, float* __restrict__ el,
                        float* __restrict__ er) {
    int w = (blockIdx.x * blockDim.x + threadIdx.x) >> 5;
    if (w >= NN) return;
    int lane = threadIdx.x & 31;
    const float2* hp = (const float2*)(h2res + (size_t)w * 128);
    float2 h = hp[lane];
    float2 av = ((const float2*)al)[lane];
    float2 rv = ((const float2*)ar)[lane];
    float a = h.x * av.x + h.y * av.y;
    float b = h.x * rv.x + h.y * rv.y;
    #pragma unroll
    for (int o = 16; o; o >>= 1) {
        a += __shfl_xor_sync(FULL, a, o);
        b += __shfl_xor_sync(FULL, b, o);
    }
    if (lane == 0) { el[w] = a; er[w] = b; }
}

// ---------------- layer-1 aggregation: single-pass, 4-edge unrolled ----------------
__global__ __launch_bounds__(256)
void k_agg1(const int* __restrict__ us, const int* __restrict__ off,
            const float* __restrict__ h1, const float* __restrict__ el,
            const float* __restrict__ er, const float* __restrict__ feats,
            const float* __restrict__ bias, float* __restrict__ x1) {
    int w = (blockIdx.x * blockDim.x + threadIdx.x) >> 5;
    if (w >= NN) return;
    int lane = threadIdx.x & 31;
    int s0 = off[w], s1 = off[w + 1];
    int hA = lane >> 3, hB = 4 + (lane >> 3);

    float er_l = (lane < 8) ? er[w * 8 + lane] : 0.f;
    float s_l = 0.f;
    float4 acc0 = make_float4(0.f, 0.f, 0.f, 0.f);
    float4 acc1 = make_float4(0.f, 0.f, 0.f, 0.f);

    int i = s0;
    for (; i + 4 <= s1; i += 4) {
        // 4 independent index loads
        int u0 = us[i], u1 = us[i + 1], u2 = us[i + 2], u3 = us[i + 3];
        // 4 independent el gathers
        float e0 = 0.f, e1 = 0.f, e2 = 0.f, e3 = 0.f;
        if (lane < 8) {
            e0 = el[u0 * 8 + lane];
            e1 = el[u1 * 8 + lane];
            e2 = el[u2 * 8 + lane];
            e3 = el[u3 * 8 + lane];
        }
        // 8 independent h-row vector loads (512 B each warp-wide)
        const float4* p0 = (const float4*)(h1 + (size_t)u0 * F1);
        const float4* p1 = (const float4*)(h1 + (size_t)u1 * F1);
        const float4* p2 = (const float4*)(h1 + (size_t)u2 * F1);
        const float4* p3 = (const float4*)(h1 + (size_t)u3 * F1);
        float4 x0 = p0[lane], y0 = p0[lane + 32];
        float4 x1v = p1[lane], y1 = p1[lane + 32];
        float4 x2 = p2[lane], y2 = p2[lane + 32];
        float4 x3 = p3[lane], y3 = p3[lane + 32];

        float t0 = e0 + er_l; t0 = t0 > 0.f ? t0 : NEG * t0;
        float t1 = e1 + er_l; t1 = t1 > 0.f ? t1 : NEG * t1;
        float t2 = e2 + er_l; t2 = t2 > 0.f ? t2 : NEG * t2;
        float t3 = e3 + er_l; t3 = t3 > 0.f ? t3 : NEG * t3;
        float w0 = __expf(t0), w1 = __expf(t1), w2 = __expf(t2), w3 = __expf(t3);
        s_l += (w0 + w1) + (w2 + w3);

        float a0A = __shfl_sync(FULL, w0, hA), a0B = __shfl_sync(FULL, w0, hB);
        float a1A = __shfl_sync(FULL, w1, hA), a1B = __shfl_sync(FULL, w1, hB);
        float a2A = __shfl_sync(FULL, w2, hA), a2B = __shfl_sync(FULL, w2, hB);
        float a3A = __shfl_sync(FULL, w3, hA), a3B = __shfl_sync(FULL, w3, hB);

        acc0.x += x0.x * a0A + x1v.x * a1A + x2.x * a2A + x3.x * a3A;
        acc0.y += x0.y * a0A + x1v.y * a1A + x2.y * a2A + x3.y * a3A;
        acc0.z += x0.z * a0A + x1v.z * a1A + x2.z * a2A + x3.z * a3A;
        acc0.w += x0.w * a0A + x1v.w * a1A + x2.w * a2A + x3.w * a3A;
        acc1.x += y0.x * a0B + y1.x * a1B + y2.x * a2B + y3.x * a3B;
        acc1.y += y0.y * a0B + y1.y * a1B + y2.y * a2B + y3.y * a3B;
        acc1.z += y0.z * a0B + y1.z * a1B + y2.z * a2B + y3.z * a3B;
        acc1.w += y0.w * a0B + y1.w * a1B + y2.w * a2B + y3.w * a3B;
    }
    for (; i < s1; i++) {
        int u = us[i];
        float e = (lane < 8) ? el[u * 8 + lane] : 0.f;
        const float4* hu = (const float4*)(h1 + (size_t)u * F1);
        float4 b0 = hu[lane], b1 = hu[lane + 32];
        float tt = e + er_l;
        tt = tt > 0.f ? tt : NEG * tt;
        float ewl = __expf(tt);
        s_l += ewl;
        float aA = __shfl_sync(FULL, ewl, hA);
        float aB = __shfl_sync(FULL, ewl, hB);
        acc0.x += b0.x * aA; acc0.y += b0.y * aA; acc0.z += b0.z * aA; acc0.w += b0.w * aA;
        acc1.x += b1.x * aB; acc1.y += b1.y * aB; acc1.z += b1.z * aB; acc1.w += b1.w * aB;
    }

    float is_l = (lane < 8) ? 1.f / s_l : 0.f;
    float isA = __shfl_sync(FULL, is_l, hA);
    float isB = __shfl_sync(FULL, is_l, hB);

    const float4* fp = (const float4*)(feats + (size_t)w * FIN);
    const float4* bp = (const float4*)bias;
    float4 f0 = fp[lane], f1 = fp[lane + 32];
    float4 bA = bp[lane], bB = bp[lane + 32];
    float4 o0, o1;
    o0.x = acc0.x * isA + f0.x + bA.x;  o0.y = acc0.y * isA + f0.y + bA.y;
    o0.z = acc0.z * isA + f0.z + bA.z;  o0.w = acc0.w * isA + f0.w + bA.w;
    o1.x = acc1.x * isB + f1.x + bB.x;  o1.y = acc1.y * isB + f1.y + bB.y;
    o1.z = acc1.z * isB + f1.z + bB.z;  o1.w = acc1.w * isB + f1.w + bB.w;
    o0.x = o0.x > 0.f ? o0.x : expm1f(o0.x);
    o0.y = o0.y > 0.f ? o0.y : expm1f(o0.y);
    o0.z = o0.z > 0.f ? o0.z : expm1f(o0.z);
    o0.w = o0.w > 0.f ? o0.w : expm1f(o0.w);
    o1.x = o1.x > 0.f ? o1.x : expm1f(o1.x);
    o1.y = o1.y > 0.f ? o1.y : expm1f(o1.y);
    o1.z = o1.z > 0.f ? o1.z : expm1f(o1.z);
    o1.w = o1.w > 0.f ? o1.w : expm1f(o1.w);
    float4* xp = (float4*)(x1 + (size_t)w * F1);
    xp[lane] = o0;
    xp[lane + 32] = o1;
}

// ---------------- concat [W2 | res_W2] ----------------
__global__ void k_concat(const float* __restrict__ W2, const float* __restrict__ rw,
                         float* __restrict__ Bcat) {
    int i = blockIdx.x * blockDim.x + threadIdx.x;
    if (i < FIN * 128) {
        int k = i >> 7, c = i & 127;
        Bcat[i] = (c < 64) ? W2[k * 64 + c] : rw[k * 64 + (c - 64)];
    }
}

// ---------------- layer-2 aggregation: single-pass, 4-edge unrolled ----------------
__global__ __launch_bounds__(256)
void k_agg2(const int* __restrict__ us, const int* __restrict__ off,
            const float* __restrict__ h2res, const float* __restrict__ el,
            const float* __restrict__ er, const float* __restrict__ bias,
            float* __restrict__ out) {
    int w = (blockIdx.x * blockDim.x + threadIdx.x) >> 5;
    if (w >= NN) return;
    int lane = threadIdx.x & 31;
    int s0 = off[w], s1 = off[w + 1];
    float erv = er[w];
    float s = 0.f;
    float2 acc = make_float2(0.f, 0.f);

    int i = s0;
    for (; i + 4 <= s1; i += 4) {
        int u0 = us[i], u1 = us[i + 1], u2 = us[i + 2], u3 = us[i + 3];
        float e0 = el[u0], e1 = el[u1], e2 = el[u2], e3 = el[u3];
        float2 b0 = *(const float2*)&h2res[(size_t)u0 * 128 + 2 * lane];
        float2 b1 = *(const float2*)&h2res[(size_t)u1 * 128 + 2 * lane];
        float2 b2 = *(const float2*)&h2res[(size_t)u2 * 128 + 2 * lane];
        float2 b3 = *(const float2*)&h2res[(size_t)u3 * 128 + 2 * lane];
        float t0 = e0 + erv; t0 = t0 > 0.f ? t0 : NEG * t0;
        float t1 = e1 + erv; t1 = t1 > 0.f ? t1 : NEG * t1;
        float t2 = e2 + erv; t2 = t2 > 0.f ? t2 : NEG * t2;
        float t3 = e3 + erv; t3 = t3 > 0.f ? t3 : NEG * t3;
        float w0 = __expf(t0), w1 = __expf(t1), w2 = __expf(t2), w3 = __expf(t3);
        s += (w0 + w1) + (w2 + w3);
        acc.x += b0.x * w0 + b1.x * w1 + b2.x * w2 + b3.x * w3;
        acc.y += b0.y * w0 + b1.y * w1 + b2.y * w2 + b3.y * w3;
    }
    for (; i < s1; i++) {
        int u = us[i];
        float tt = el[u] + erv;
        tt = tt > 0.f ? tt : NEG * tt;
        float e = __expf(tt);
        s += e;
        float2 b = *(const float2*)&h2res[(size_t)u * 128 + 2 * lane];
        acc.x += b.x * e;
        acc.y += b.y * e;
    }
    float is = 1.f / s;
    float2 rv = *(const float2*)&h2res[(size_t)w * 128 + 64 + 2 * lane];
    float2 bv = *(const float2*)&bias[2 * lane];
    float2 o;
    o.x = acc.x * is + rv.x + bv.x;
    o.y = acc.y * is + rv.y + bv.y;
    *(float2*)&out[(size_t)w * 64 + 2 * lane] = o;
}

// ---------------- launch ----------------
extern "C" void kernel_launch(void* const* d_in, const int* in_sizes, int n_in,
                              void* d_out, int out_size) {
    const float* feats = (const float*)d_in[0];
    const int*   src   = (const int*)d_in[1];
    const int*   dst   = (const int*)d_in[2];
    const float* W1    = (const float*)d_in[3];
    const float* al1   = (const float*)d_in[4];
    const float* ar1   = (const float*)d_in[5];
    const float* b1    = (const float*)d_in[6];
    const float* W2    = (const float*)d_in[7];
    const float* al2   = (const float*)d_in[8];
    const float* ar2   = (const float*)d_in[9];
    const float* b2    = (const float*)d_in[10];
    const float* rw2   = (const float*)d_in[11];
    float* out = (float*)d_out;
    int E = in_sizes[1];

    float *h1, *el1, *er1, *x1, *h2res, *el2, *er2, *Bcat;
    int *deg, *off, *us;
    cudaGetSymbolAddress((void**)&h1, g_h1);
    cudaGetSymbolAddress((void**)&el1, g_el1);
    cudaGetSymbolAddress((void**)&er1, g_er1);
    cudaGetSymbolAddress((void**)&x1, g_x1);
    cudaGetSymbolAddress((void**)&h2res, g_h2res);
    cudaGetSymbolAddress((void**)&el2, g_el2);
    cudaGetSymbolAddress((void**)&er2, g_er2);
    cudaGetSymbolAddress((void**)&Bcat, g_Bcat);
    cudaGetSymbolAddress((void**)&deg, g_deg);
    cudaGetSymbolAddress((void**)&off, g_off);
    cudaGetSymbolAddress((void**)&us, g_us);

    static cudaStream_t side = nullptr;
    static cudaEvent_t evFork = nullptr, evJoin = nullptr;
    if (!side) {
        cudaStreamCreateWithFlags(&side, cudaStreamNonBlocking);
        cudaEventCreateWithFlags(&evFork, cudaEventDisableTiming);
        cudaEventCreateWithFlags(&evJoin, cudaEventDisableTiming);
    }

    int eb = (E + 255) / 256;
    int wb = (NN * 32 + 255) / 256;

    // fork: CSR build + weight concat on side stream
    cudaEventRecord(evFork, 0);
    cudaStreamWaitEvent(side, evFork, 0);
    cudaMemsetAsync(deg, 0, NN * sizeof(int), side);
    k_hist<<<eb, 256, 0, side>>>(dst, E, deg);
    k_scan<<<1, 1024, 0, side>>>(deg, off, NN);
    cudaMemsetAsync(deg, 0, NN * sizeof(int), side);
    k_scatter<<<eb, 256, 0, side>>>(src, dst, E, off, deg, us);
    k_concat<<<(FIN * 128 + 255) / 256, 256, 0, side>>>(W2, rw2, Bcat);
    cudaEventRecord(evJoin, side);

    // main stream: layer-1 dense part
    k_mma_gemm<<<dim3((NN + 127) / 128, F1 / 64), 256>>>(feats, W1, h1, NN, F1, FIN);
    k_attn1<<<wb, 256>>>(h1, al1, ar1, el1, er1);

    cudaStreamWaitEvent(0, evJoin, 0);
    k_agg1<<<wb, 256>>>(us, off, h1, el1, er1, feats, b1, x1);

    // layer 2
    k_mma_gemm<<<dim3((NN + 127) / 128, 128 / 64), 256>>>(x1, Bcat, h2res, NN, 128, FIN);
    k_attn2<<<wb, 256>>>(h2res, al2, ar2, el2, er2);
    k_agg2<<<wb, 256>>>(us, off, h2res, el2, er2, b2, out);
}